// round 1
// baseline (speedup 1.0000x reference)
#include <cuda_runtime.h>

// LSTM_87067577025240 — Round 1: exact-fp32 persistent baseline using packed
// fma.rn.f32x2 (sm_103a FFMA2). 128 CTAs x 512 threads, each CTA owns 16 batch
// columns for all 256 timesteps (batch columns are independent -> no inter-CTA
// sync). Weights pre-transposed once per launch into a gate-fused float4
// buffer for coalesced LDG.128 in the k-loop.

#define SEQ   256
#define H     512
#define B_TOT 2048
#define C_OUT 10
#define NB    16                  // batch columns per CTA
#define NCTA  (B_TOT / NB)        // 128 CTAs
#define NPAIR (NB / 2)            // 8 f32x2 pairs

typedef unsigned long long u64;

// Gate-fused transposed weights: g_Wt[k*H + t] = {wgh[t][k], wih[t][k], wfh[t][k], woh[t][k]}
__device__ float4 g_Wt[H * H];

__device__ __forceinline__ u64 pack2(float lo, float hi) {
    u64 r;
    asm("mov.b64 %0, {%1, %2};" : "=l"(r) : "f"(lo), "f"(hi));
    return r;
}
__device__ __forceinline__ void unpack2(u64 v, float &lo, float &hi) {
    asm("mov.b64 {%0, %1}, %2;" : "=f"(lo), "=f"(hi) : "l"(v));
}
__device__ __forceinline__ u64 fma2(u64 a, u64 b, u64 c) {
    u64 d;
    asm("fma.rn.f32x2 %0, %1, %2, %3;" : "=l"(d) : "l"(a), "l"(b), "l"(c));
    return d;
}

// sigmoid / tanh built on MUFU.EX2 (rel err ~2^-22); avoids tanh.approx (2^-11)
// which fast-math would substitute for tanhf and which compounds over 256 steps.
__device__ __forceinline__ float sigmoid_f(float x) {
    return 1.0f / (1.0f + __expf(-x));
}
__device__ __forceinline__ float tanh_f(float x) {
    float ax = fabsf(x);
    float e  = __expf(-2.0f * ax);
    float t  = (1.0f - e) / (1.0f + e);
    return copysignf(t, x);
}

__global__ void prepack_kernel(const float* __restrict__ wgh,
                               const float* __restrict__ wih,
                               const float* __restrict__ wfh,
                               const float* __restrict__ woh) {
    int id = blockIdx.x * blockDim.x + threadIdx.x;   // [0, H*H)
    int k  = id & (H - 1);
    int t  = id >> 9;
    // coalesced reads (k fastest), scattered 16B writes (one-time-per-replay, cheap)
    g_Wt[k * H + t] = make_float4(wgh[t * H + k], wih[t * H + k],
                                  wfh[t * H + k], woh[t * H + k]);
}

__global__ __launch_bounds__(H, 1)
void lstm_kernel(const float* __restrict__ x,
                 const float* __restrict__ wgx, const float* __restrict__ wix,
                 const float* __restrict__ wfx, const float* __restrict__ wox,
                 const float* __restrict__ bg,  const float* __restrict__ bi,
                 const float* __restrict__ bf,  const float* __restrict__ bo,
                 const float* __restrict__ wph, const float* __restrict__ bp,
                 const float* __restrict__ h_init, const float* __restrict__ c_init,
                 float* __restrict__ out) {
    __shared__ __align__(16) float hs[H * NB];  // h[k][j], broadcast-read in k-loop
    __shared__ __align__(16) float cs[H * NB];  // c state per (row, col)
    __shared__ float xs[NB];

    const int t    = threadIdx.x;        // h-row owned by this thread
    const int base = blockIdx.x * NB;    // first batch column of this CTA

    // per-row constants
    const float wgx_r = wgx[t], wix_r = wix[t], wfx_r = wfx[t], wox_r = wox[t];
    const float bg_r  = bg[t],  bi_r  = bi[t],  bf_r  = bf[t],  bo_r  = bo[t];

    const float h0 = h_init[t];
    const float c0 = c_init[t];
#pragma unroll
    for (int j = 0; j < NB; j++) {
        hs[t * NB + j] = h0;
        cs[t * NB + j] = c0;
    }
    __syncthreads();

    for (int s = 0; s < SEQ; s++) {
        if (t < NB) xs[t] = x[(base + t) * SEQ + s];

        u64 ag[NPAIR], ai[NPAIR], af[NPAIR], ao[NPAIR];
#pragma unroll
        for (int jp = 0; jp < NPAIR; jp++) { ag[jp] = 0ULL; ai[jp] = 0ULL; af[jp] = 0ULL; ao[jp] = 0ULL; }

        // gate pre-activations: acc[gate][j] += W[gate][t][k] * h[k][j]
#pragma unroll 4
        for (int k = 0; k < H; k++) {
            const float4 w = g_Wt[k * H + t];             // LDG.128, coalesced over t
            const u64 wg2 = pack2(w.x, w.x);
            const u64 wi2 = pack2(w.y, w.y);
            const u64 wf2 = pack2(w.z, w.z);
            const u64 wo2 = pack2(w.w, w.w);
            const u64* hp = reinterpret_cast<const u64*>(&hs[k * NB]); // broadcast LDS.64
#pragma unroll
            for (int jp = 0; jp < NPAIR; jp++) {
                const u64 h2 = hp[jp];
                ag[jp] = fma2(wg2, h2, ag[jp]);
                ai[jp] = fma2(wi2, h2, ai[jp]);
                af[jp] = fma2(wf2, h2, af[jp]);
                ao[jp] = fma2(wo2, h2, ao[jp]);
            }
        }
        __syncthreads();   // everyone done reading hs before we overwrite it

        // elementwise: gates -> (c, h) update for this thread's row
#pragma unroll
        for (int jp = 0; jp < NPAIR; jp++) {
            float pg0, pg1, pi0, pi1, pf0, pf1, po0, po1;
            unpack2(ag[jp], pg0, pg1);
            unpack2(ai[jp], pi0, pi1);
            unpack2(af[jp], pf0, pf1);
            unpack2(ao[jp], po0, po1);
#pragma unroll
            for (int hhalf = 0; hhalf < 2; hhalf++) {
                const int j  = jp * 2 + hhalf;
                const float pg = (hhalf ? pg1 : pg0);
                const float pi = (hhalf ? pi1 : pi0);
                const float pf = (hhalf ? pf1 : pf0);
                const float po = (hhalf ? po1 : po0);
                const float xv = xs[j];
                const float g = tanh_f   (pg + wgx_r * xv + bg_r);
                const float i = sigmoid_f(pi + wix_r * xv + bi_r);
                const float f = sigmoid_f(pf + wfx_r * xv + bf_r);
                const float o = sigmoid_f(po + wox_r * xv + bo_r);
                float c = cs[t * NB + j];
                c = g * i + c * f;
                cs[t * NB + j] = c;
                hs[t * NB + j] = tanh_f(c) * o;
            }
        }
        __syncthreads();   // hs(t+1) complete before next step's k-loop / next xs write
    }

    // final projection: out[b][c] = wph[c][:] . h[:, b] + bp[c]
    if (t < NB * C_OUT) {
        const int j = t / C_OUT;
        const int c = t % C_OUT;
        float acc = bp[c];
#pragma unroll 8
        for (int k = 0; k < H; k++) acc += wph[c * H + k] * hs[k * NB + j];
        out[(base + j) * C_OUT + c] = acc;
    }
}

extern "C" void kernel_launch(void* const* d_in, const int* in_sizes, int n_in,
                              void* d_out, int out_size) {
    const float* x      = (const float*)d_in[0];
    const float* wgx    = (const float*)d_in[1];
    const float* wix    = (const float*)d_in[2];
    const float* wfx    = (const float*)d_in[3];
    const float* wox    = (const float*)d_in[4];
    const float* wgh    = (const float*)d_in[5];
    const float* wih    = (const float*)d_in[6];
    const float* wfh    = (const float*)d_in[7];
    const float* woh    = (const float*)d_in[8];
    const float* bg     = (const float*)d_in[9];
    const float* bi     = (const float*)d_in[10];
    const float* bf     = (const float*)d_in[11];
    const float* bo     = (const float*)d_in[12];
    const float* wph    = (const float*)d_in[13];
    const float* bp     = (const float*)d_in[14];
    const float* h_init = (const float*)d_in[15];
    const float* c_init = (const float*)d_in[16];
    float* out = (float*)d_out;

    prepack_kernel<<<(H * H) / 256, 256>>>(wgh, wih, wfh, woh);
    lstm_kernel<<<NCTA, H>>>(x, wgx, wix, wfx, wox, bg, bi, bf, bo,
                             wph, bp, h_init, c_init, out);
}

// round 2
// speedup vs baseline: 1.0002x; 1.0002x over previous
#include <cuda_runtime.h>

// LSTM_87067577025240 — Round 1: exact-fp32 persistent baseline using packed
// fma.rn.f32x2 (sm_103a FFMA2). 128 CTAs x 512 threads, each CTA owns 16 batch
// columns for all 256 timesteps (batch columns are independent -> no inter-CTA
// sync). Weights pre-transposed once per launch into a gate-fused float4
// buffer for coalesced LDG.128 in the k-loop.

#define SEQ   256
#define H     512
#define B_TOT 2048
#define C_OUT 10
#define NB    16                  // batch columns per CTA
#define NCTA  (B_TOT / NB)        // 128 CTAs
#define NPAIR (NB / 2)            // 8 f32x2 pairs

typedef unsigned long long u64;

// Gate-fused transposed weights: g_Wt[k*H + t] = {wgh[t][k], wih[t][k], wfh[t][k], woh[t][k]}
__device__ float4 g_Wt[H * H];

__device__ __forceinline__ u64 pack2(float lo, float hi) {
    u64 r;
    asm("mov.b64 %0, {%1, %2};" : "=l"(r) : "f"(lo), "f"(hi));
    return r;
}
__device__ __forceinline__ void unpack2(u64 v, float &lo, float &hi) {
    asm("mov.b64 {%0, %1}, %2;" : "=f"(lo), "=f"(hi) : "l"(v));
}
__device__ __forceinline__ u64 fma2(u64 a, u64 b, u64 c) {
    u64 d;
    asm("fma.rn.f32x2 %0, %1, %2, %3;" : "=l"(d) : "l"(a), "l"(b), "l"(c));
    return d;
}

// sigmoid / tanh built on MUFU.EX2 (rel err ~2^-22); avoids tanh.approx (2^-11)
// which fast-math would substitute for tanhf and which compounds over 256 steps.
__device__ __forceinline__ float sigmoid_f(float x) {
    return 1.0f / (1.0f + __expf(-x));
}
__device__ __forceinline__ float tanh_f(float x) {
    float ax = fabsf(x);
    float e  = __expf(-2.0f * ax);
    float t  = (1.0f - e) / (1.0f + e);
    return copysignf(t, x);
}

__global__ void prepack_kernel(const float* __restrict__ wgh,
                               const float* __restrict__ wih,
                               const float* __restrict__ wfh,
                               const float* __restrict__ woh) {
    int id = blockIdx.x * blockDim.x + threadIdx.x;   // [0, H*H)
    int k  = id & (H - 1);
    int t  = id >> 9;
    // coalesced reads (k fastest), scattered 16B writes (one-time-per-replay, cheap)
    g_Wt[k * H + t] = make_float4(wgh[t * H + k], wih[t * H + k],
                                  wfh[t * H + k], woh[t * H + k]);
}

__global__ __launch_bounds__(H, 1)
void lstm_kernel(const float* __restrict__ x,
                 const float* __restrict__ wgx, const float* __restrict__ wix,
                 const float* __restrict__ wfx, const float* __restrict__ wox,
                 const float* __restrict__ bg,  const float* __restrict__ bi,
                 const float* __restrict__ bf,  const float* __restrict__ bo,
                 const float* __restrict__ wph, const float* __restrict__ bp,
                 const float* __restrict__ h_init, const float* __restrict__ c_init,
                 float* __restrict__ out) {
    __shared__ __align__(16) float hs[H * NB];  // h[k][j], broadcast-read in k-loop
    __shared__ __align__(16) float cs[H * NB];  // c state per (row, col)
    __shared__ float xs[NB];

    const int t    = threadIdx.x;        // h-row owned by this thread
    const int base = blockIdx.x * NB;    // first batch column of this CTA

    // per-row constants
    const float wgx_r = wgx[t], wix_r = wix[t], wfx_r = wfx[t], wox_r = wox[t];
    const float bg_r  = bg[t],  bi_r  = bi[t],  bf_r  = bf[t],  bo_r  = bo[t];

    const float h0 = h_init[t];
    const float c0 = c_init[t];
#pragma unroll
    for (int j = 0; j < NB; j++) {
        hs[t * NB + j] = h0;
        cs[t * NB + j] = c0;
    }
    __syncthreads();

    for (int s = 0; s < SEQ; s++) {
        if (t < NB) xs[t] = x[(base + t) * SEQ + s];

        u64 ag[NPAIR], ai[NPAIR], af[NPAIR], ao[NPAIR];
#pragma unroll
        for (int jp = 0; jp < NPAIR; jp++) { ag[jp] = 0ULL; ai[jp] = 0ULL; af[jp] = 0ULL; ao[jp] = 0ULL; }

        // gate pre-activations: acc[gate][j] += W[gate][t][k] * h[k][j]
#pragma unroll 4
        for (int k = 0; k < H; k++) {
            const float4 w = g_Wt[k * H + t];             // LDG.128, coalesced over t
            const u64 wg2 = pack2(w.x, w.x);
            const u64 wi2 = pack2(w.y, w.y);
            const u64 wf2 = pack2(w.z, w.z);
            const u64 wo2 = pack2(w.w, w.w);
            const u64* hp = reinterpret_cast<const u64*>(&hs[k * NB]); // broadcast LDS.64
#pragma unroll
            for (int jp = 0; jp < NPAIR; jp++) {
                const u64 h2 = hp[jp];
                ag[jp] = fma2(wg2, h2, ag[jp]);
                ai[jp] = fma2(wi2, h2, ai[jp]);
                af[jp] = fma2(wf2, h2, af[jp]);
                ao[jp] = fma2(wo2, h2, ao[jp]);
            }
        }
        __syncthreads();   // everyone done reading hs before we overwrite it

        // elementwise: gates -> (c, h) update for this thread's row
#pragma unroll
        for (int jp = 0; jp < NPAIR; jp++) {
            float pg0, pg1, pi0, pi1, pf0, pf1, po0, po1;
            unpack2(ag[jp], pg0, pg1);
            unpack2(ai[jp], pi0, pi1);
            unpack2(af[jp], pf0, pf1);
            unpack2(ao[jp], po0, po1);
#pragma unroll
            for (int hhalf = 0; hhalf < 2; hhalf++) {
                const int j  = jp * 2 + hhalf;
                const float pg = (hhalf ? pg1 : pg0);
                const float pi = (hhalf ? pi1 : pi0);
                const float pf = (hhalf ? pf1 : pf0);
                const float po = (hhalf ? po1 : po0);
                const float xv = xs[j];
                const float g = tanh_f   (pg + wgx_r * xv + bg_r);
                const float i = sigmoid_f(pi + wix_r * xv + bi_r);
                const float f = sigmoid_f(pf + wfx_r * xv + bf_r);
                const float o = sigmoid_f(po + wox_r * xv + bo_r);
                float c = cs[t * NB + j];
                c = g * i + c * f;
                cs[t * NB + j] = c;
                hs[t * NB + j] = tanh_f(c) * o;
            }
        }
        __syncthreads();   // hs(t+1) complete before next step's k-loop / next xs write
    }

    // final projection: out[b][c] = wph[c][:] . h[:, b] + bp[c]
    if (t < NB * C_OUT) {
        const int j = t / C_OUT;
        const int c = t % C_OUT;
        float acc = bp[c];
#pragma unroll 8
        for (int k = 0; k < H; k++) acc += wph[c * H + k] * hs[k * NB + j];
        out[(base + j) * C_OUT + c] = acc;
    }
}

extern "C" void kernel_launch(void* const* d_in, const int* in_sizes, int n_in,
                              void* d_out, int out_size) {
    const float* x      = (const float*)d_in[0];
    const float* wgx    = (const float*)d_in[1];
    const float* wix    = (const float*)d_in[2];
    const float* wfx    = (const float*)d_in[3];
    const float* wox    = (const float*)d_in[4];
    const float* wgh    = (const float*)d_in[5];
    const float* wih    = (const float*)d_in[6];
    const float* wfh    = (const float*)d_in[7];
    const float* woh    = (const float*)d_in[8];
    const float* bg     = (const float*)d_in[9];
    const float* bi     = (const float*)d_in[10];
    const float* bf     = (const float*)d_in[11];
    const float* bo     = (const float*)d_in[12];
    const float* wph    = (const float*)d_in[13];
    const float* bp     = (const float*)d_in[14];
    const float* h_init = (const float*)d_in[15];
    const float* c_init = (const float*)d_in[16];
    float* out = (float*)d_out;

    prepack_kernel<<<(H * H) / 256, 256>>>(wgh, wih, wfh, woh);
    lstm_kernel<<<NCTA, H>>>(x, wgx, wix, wfx, wox, bg, bi, bf, bo,
                             wph, bp, h_init, c_init, out);
}